// round 12
// baseline (speedup 1.0000x reference)
#include <cuda_runtime.h>

// Problem constants (static per reference)
#define BSZ   128
#define NTOT  129
#define NPT   128          // N
#define GS    16
#define CH    384          // channels
#define CH4   96           // CH / 4 (float4 units per row)
#define EPSW  0.05f
#define RMSEPS 1e-6f

__global__ __launch_bounds__(96, 13)
void K_Rectify_38216619000515_kernel(
    const float* __restrict__ f,        // (B, NTOT, CH)
    const float* __restrict__ distance, // (B, N, GS)
    const float* __restrict__ rf,       // (NTOT, CH)
    const float* __restrict__ knorm_w,  // (CH,)
    const int*   __restrict__ idx,      // (B, N, GS), int32, values in [0, B*N)
    float*       __restrict__ out)      // (B, NTOT, CH)
{
    const int bid = blockIdx.x;          // 0..8191, two points per block
    const int bn0 = bid << 1;
    const int bn1 = bn0 | 1;
    const int tid = threadIdx.x;         // 0..95
    const int w   = tid >> 5;
    const int lane = tid & 31;

    __shared__ float4 sgw[GS];           // (offA bits, wtA, offB bits, wtB), offsets in float4 units
    __shared__ float  red[2][3];

    if (tid < 2 * GS) {
        const int p  = tid >> 4;         // point 0/1
        const int g  = tid & 15;
        const int bn = bn0 + p;
        float d  = distance[bn * GS + g];
        float wt = 1.0f / (d + EPSW);
        int r    = idx[bn * GS + g] & (BSZ * NPT - 1);
        int off  = ((r >> 7) * NTOT + (r & 127) + 1) * CH4;   // float4 units
        if (p == 0) { sgw[g].x = __int_as_float(off); sgw[g].y = wt; }
        else        { sgw[g].z = __int_as_float(off); sgw[g].w = wt; }
    }

    const int b0 = bn0 >> 7, n0 = bn0 & 127;
    const int n1 = n0 | 1;               // same b, odd n -> never cls

    // cls token passthrough (only point A can have n==0); 96 lanes == CH4
    if (n0 == 0) {
        __stcs((float4*)out + b0 * (NTOT * CH4) + tid,
               __ldg((const float4*)f + b0 * (NTOT * CH4) + tid));
    }
    __syncthreads();

    float wsA = 0.0f, wsB = 0.0f;
#pragma unroll
    for (int g = 0; g < GS; ++g) { wsA += sgw[g].y; wsB += sgw[g].w; }
    const float iwA = 1.0f / wsA;
    const float iwB = 1.0f / wsB;

    const float4* f4 = (const float4*)f;
    const int xrowA = (b0 * NTOT + 1 + n0) * CH4;
    const int xrowB = (b0 * NTOT + 1 + n1) * CH4;

    float4 sa = make_float4(0.f,0.f,0.f,0.f);
    float4 sb = make_float4(0.f,0.f,0.f,0.f);

    // first 12 gather rows
#pragma unroll
    for (int g = 0; g < 12; ++g) {
        const float4 q = sgw[g];                 // one LDS.128 broadcast per g
        const float4 va = __ldg(f4 + __float_as_int(q.x) + tid);
        const float4 vb = __ldg(f4 + __float_as_int(q.z) + tid);
        const float wa = q.y, wb = q.w;
        sa.x = fmaf(wa, va.x, sa.x); sa.y = fmaf(wa, va.y, sa.y);
        sa.z = fmaf(wa, va.z, sa.z); sa.w = fmaf(wa, va.w, sa.w);
        sb.x = fmaf(wb, vb.x, sb.x); sb.y = fmaf(wb, vb.y, sb.y);
        sb.z = fmaf(wb, vb.z, sb.z); sb.w = fmaf(wb, vb.w, sb.w);
    }
    // x loads join the final batch
    const float4 xa = __ldg(f4 + xrowA + tid);
    const float4 xb = __ldg(f4 + xrowB + tid);
    // last 4 gather rows
#pragma unroll
    for (int g = 12; g < GS; ++g) {
        const float4 q = sgw[g];
        const float4 va = __ldg(f4 + __float_as_int(q.x) + tid);
        const float4 vb = __ldg(f4 + __float_as_int(q.z) + tid);
        const float wa = q.y, wb = q.w;
        sa.x = fmaf(wa, va.x, sa.x); sa.y = fmaf(wa, va.y, sa.y);
        sa.z = fmaf(wa, va.z, sa.z); sa.w = fmaf(wa, va.w, sa.w);
        sb.x = fmaf(wb, vb.x, sb.x); sb.y = fmaf(wb, vb.y, sb.y);
        sb.z = fmaf(wb, vb.z, sb.z); sb.w = fmaf(wb, vb.w, sb.w);
    }

    // (sum w*row)/W - x   (weights normalized in reference)
    sa.x = sa.x*iwA - xa.x; sa.y = sa.y*iwA - xa.y;
    sa.z = sa.z*iwA - xa.z; sa.w = sa.w*iwA - xa.w;
    sb.x = sb.x*iwB - xb.x; sb.y = sb.y*iwB - xb.y;
    sb.z = sb.z*iwB - xb.z; sb.w = sb.w*iwB - xb.w;

    float lA = sa.x*sa.x + sa.y*sa.y + sa.z*sa.z + sa.w*sa.w;
    float lB = sb.x*sb.x + sb.y*sb.y + sb.z*sb.z + sb.w*sb.w;

#pragma unroll
    for (int off = 16; off > 0; off >>= 1) {
        lA += __shfl_down_sync(0xffffffffu, lA, off);
        lB += __shfl_down_sync(0xffffffffu, lB, off);
    }
    if (lane == 0) { red[0][w] = lA; red[1][w] = lB; }
    __syncthreads();
    const float riA = rsqrtf((red[0][0] + red[0][1] + red[0][2]) * (1.0f / CH) + RMSEPS);
    const float riB = rsqrtf((red[1][0] + red[1][1] + red[1][2]) * (1.0f / CH) + RMSEPS);

    const float4 kv  = __ldg((const float4*)knorm_w + tid);
    const float4 rvA = __ldg((const float4*)rf + (1 + n0) * CH4 + tid);
    const float4 rvB = __ldg((const float4*)rf + (1 + n1) * CH4 + tid);

    float4 o;
    o.x = rvA.x + xa.x + sa.x*riA*kv.x;  o.y = rvA.y + xa.y + sa.y*riA*kv.y;
    o.z = rvA.z + xa.z + sa.z*riA*kv.z;  o.w = rvA.w + xa.w + sa.w*riA*kv.w;
    __stcs((float4*)out + xrowA + tid, o);
    o.x = rvB.x + xb.x + sb.x*riB*kv.x;  o.y = rvB.y + xb.y + sb.y*riB*kv.y;
    o.z = rvB.z + xb.z + sb.z*riB*kv.z;  o.w = rvB.w + xb.w + sb.w*riB*kv.w;
    __stcs((float4*)out + xrowB + tid, o);
}

extern "C" void kernel_launch(void* const* d_in, const int* in_sizes, int n_in,
                              void* d_out, int out_size)
{
    const float* f        = (const float*)d_in[0];
    const float* distance = (const float*)d_in[1];
    const float* rf       = (const float*)d_in[2];
    const float* knorm_w  = (const float*)d_in[3];
    const int*   idx      = (const int*)d_in[4];
    float*       out      = (float*)d_out;

    K_Rectify_38216619000515_kernel<<<(BSZ * NPT) / 2, 96>>>(
        f, distance, rf, knorm_w, idx, out);
}

// round 13
// speedup vs baseline: 1.4031x; 1.4031x over previous
#include <cuda_runtime.h>

// Problem constants (static per reference)
#define BSZ   128
#define NTOT  129
#define NPT   128          // N
#define GS    16
#define CH    384          // channels
#define CH4   96           // CH / 4
#define EPSW  0.05f
#define RMSEPS 1e-6f

__global__ __launch_bounds__(96, 12)
void K_Rectify_38216619000515_kernel(
    const float* __restrict__ f,        // (B, NTOT, CH)
    const float* __restrict__ distance, // (B, N, GS)
    const float* __restrict__ rf,       // (NTOT, CH)
    const float* __restrict__ knorm_w,  // (CH,)
    const int*   __restrict__ idx,      // (B, N, GS), int32, values in [0, B*N)
    float*       __restrict__ out)      // (B, NTOT, CH)
{
    const int bid = blockIdx.x;          // 0..8191, two points per block
    const int bn0 = bid << 1;
    const int bn1 = bn0 | 1;
    const int tid = threadIdx.x;         // 0..95
    const int w   = tid >> 5;
    const int lane = tid & 31;

    __shared__ float2 sgw[2][GS];        // {row offset (int bits), weight}
    __shared__ float  red[2][3];

    if (tid < 2 * GS) {
        const int p  = tid >> 4;         // point 0/1
        const int g  = tid & 15;
        const int bn = bn0 + p;
        float d  = distance[bn * GS + g];
        float wt = 1.0f / (d + EPSW);
        int r    = idx[bn * GS + g] & (BSZ * NPT - 1);
        int off  = ((r >> 7) * NTOT + (r & 127) + 1) * CH4;   // float4 units
        sgw[p][g] = make_float2(__int_as_float(off), wt);
    }

    const int b0 = bn0 >> 7, n0 = bn0 & 127;
    const int b1 = bn1 >> 7, n1 = bn1 & 127;   // n1 is odd -> never 0

    // cls token passthrough (only point A can have n==0); 96 lanes == CH4
    if (n0 == 0) {
        __stcs((float4*)out + b0 * (NTOT * CH4) + tid,
               __ldg((const float4*)f + b0 * (NTOT * CH4) + tid));
    }
    __syncthreads();

    float wsumA = 0.0f, wsumB = 0.0f;
#pragma unroll
    for (int g = 0; g < GS; ++g) { wsumA += sgw[0][g].y; wsumB += sgw[1][g].y; }
    const float invwA = 1.0f / wsumA;
    const float invwB = 1.0f / wsumB;

    const float4* f4 = (const float4*)f;
    const int xrowA = (b0 * NTOT + 1 + n0) * CH4;
    const int xrowB = (b1 * NTOT + 1 + n1) * CH4;

    float4 sa = make_float4(0.f,0.f,0.f,0.f);
    float4 sb = make_float4(0.f,0.f,0.f,0.f);
#pragma unroll
    for (int g = 0; g < GS; ++g) {
        const float2 ga = sgw[0][g];
        const float2 gb = sgw[1][g];
        const float4 va = __ldg(f4 + __float_as_int(ga.x) + tid);
        const float4 vb = __ldg(f4 + __float_as_int(gb.x) + tid);
        const float wa = ga.y, wb = gb.y;
        sa.x = fmaf(wa, va.x, sa.x); sa.y = fmaf(wa, va.y, sa.y);
        sa.z = fmaf(wa, va.z, sa.z); sa.w = fmaf(wa, va.w, sa.w);
        sb.x = fmaf(wb, vb.x, sb.x); sb.y = fmaf(wb, vb.y, sb.y);
        sb.z = fmaf(wb, vb.z, sb.z); sb.w = fmaf(wb, vb.w, sb.w);
    }
    const float4 xa = __ldg(f4 + xrowA + tid);
    const float4 xb = __ldg(f4 + xrowB + tid);

    // (sum w*row)/W - x   (weights normalized in reference)
    sa.x = sa.x * invwA - xa.x;  sa.y = sa.y * invwA - xa.y;
    sa.z = sa.z * invwA - xa.z;  sa.w = sa.w * invwA - xa.w;
    sb.x = sb.x * invwB - xb.x;  sb.y = sb.y * invwB - xb.y;
    sb.z = sb.z * invwB - xb.z;  sb.w = sb.w * invwB - xb.w;

    float lA = sa.x*sa.x + sa.y*sa.y + sa.z*sa.z + sa.w*sa.w;
    float lB = sb.x*sb.x + sb.y*sb.y + sb.z*sb.z + sb.w*sb.w;

#pragma unroll
    for (int off = 16; off > 0; off >>= 1) {
        lA += __shfl_down_sync(0xffffffffu, lA, off);
        lB += __shfl_down_sync(0xffffffffu, lB, off);
    }
    if (lane == 0) { red[0][w] = lA; red[1][w] = lB; }
    __syncthreads();
    const float rinvA = rsqrtf((red[0][0] + red[0][1] + red[0][2]) * (1.0f / CH) + RMSEPS);
    const float rinvB = rsqrtf((red[1][0] + red[1][1] + red[1][2]) * (1.0f / CH) + RMSEPS);

    const float4 kv  = __ldg((const float4*)knorm_w + tid);
    const float4 rvA = __ldg((const float4*)rf + (1 + n0) * CH4 + tid);
    const float4 rvB = __ldg((const float4*)rf + (1 + n1) * CH4 + tid);

    float4 oA, oB;
    oA.x = rvA.x + xa.x + sa.x * rinvA * kv.x;
    oA.y = rvA.y + xa.y + sa.y * rinvA * kv.y;
    oA.z = rvA.z + xa.z + sa.z * rinvA * kv.z;
    oA.w = rvA.w + xa.w + sa.w * rinvA * kv.w;
    oB.x = rvB.x + xb.x + sb.x * rinvB * kv.x;
    oB.y = rvB.y + xb.y + sb.y * rinvB * kv.y;
    oB.z = rvB.z + xb.z + sb.z * rinvB * kv.z;
    oB.w = rvB.w + xb.w + sb.w * rinvB * kv.w;
    __stcs((float4*)out + xrowA + tid, oA);
    __stcs((float4*)out + xrowB + tid, oB);
}

extern "C" void kernel_launch(void* const* d_in, const int* in_sizes, int n_in,
                              void* d_out, int out_size)
{
    const float* f        = (const float*)d_in[0];
    const float* distance = (const float*)d_in[1];
    const float* rf       = (const float*)d_in[2];
    const float* knorm_w  = (const float*)d_in[3];
    const int*   idx      = (const int*)d_in[4];
    float*       out      = (float*)d_out;

    K_Rectify_38216619000515_kernel<<<(BSZ * NPT) / 2, 96>>>(
        f, distance, rf, knorm_w, idx, out);
}

// round 14
// speedup vs baseline: 1.4821x; 1.0563x over previous
#include <cuda_runtime.h>

// Problem constants (static per reference)
#define BSZ   128
#define NTOT  129
#define NPT   128          // N
#define GS    16
#define CH    384          // channels
#define CH4   96           // CH / 4
#define EPSW  0.05f
#define RMSEPS 1e-6f

__global__ __launch_bounds__(96, 12)
void K_Rectify_38216619000515_kernel(
    const float* __restrict__ f,        // (B, NTOT, CH)
    const float* __restrict__ distance, // (B, N, GS)
    const float* __restrict__ rf,       // (NTOT, CH)
    const float* __restrict__ knorm_w,  // (CH,)
    const int*   __restrict__ idx,      // (B, N, GS), int32, values in [0, B*N)
    float*       __restrict__ out)      // (B, NTOT, CH)
{
    const int bid = blockIdx.x;          // 0..8191, two points per block
    const int bn0 = bid << 1;
    const int bn1 = bn0 | 1;
    const int tid = threadIdx.x;         // 0..95
    const int w   = tid >> 5;
    const int lane = tid & 31;

    __shared__ float2 sgw[2][GS];        // {row offset (int bits), weight}
    __shared__ float  red[2][3];

    if (tid < 2 * GS) {
        const int p  = tid >> 4;         // point 0/1
        const int g  = tid & 15;
        const int bn = bn0 + p;
        float d  = distance[bn * GS + g];
        float wt = 1.0f / (d + EPSW);
        int r    = idx[bn * GS + g] & (BSZ * NPT - 1);
        int off  = ((r >> 7) * NTOT + (r & 127) + 1) * CH4;   // float4 units
        sgw[p][g] = make_float2(__int_as_float(off), wt);
    }

    const int b0 = bn0 >> 7, n0 = bn0 & 127;
    const int b1 = bn1 >> 7, n1 = bn1 & 127;   // n1 is odd -> never 0

    // cls token passthrough (only point A can have n==0); 96 lanes == CH4
    if (n0 == 0) {
        ((float4*)out)[b0 * (NTOT * CH4) + tid] =
            __ldg((const float4*)f + b0 * (NTOT * CH4) + tid);
    }
    __syncthreads();

    float wsumA = 0.0f, wsumB = 0.0f;
#pragma unroll
    for (int g = 0; g < GS; ++g) { wsumA += sgw[0][g].y; wsumB += sgw[1][g].y; }
    const float invwA = 1.0f / wsumA;
    const float invwB = 1.0f / wsumB;

    const float4* f4 = (const float4*)f;
    const int xrowA = (b0 * NTOT + 1 + n0) * CH4;
    const int xrowB = (b1 * NTOT + 1 + n1) * CH4;

    float4 sa = make_float4(0.f,0.f,0.f,0.f);
    float4 sb = make_float4(0.f,0.f,0.f,0.f);
#pragma unroll
    for (int g = 0; g < GS; ++g) {
        const float2 ga = sgw[0][g];
        const float2 gb = sgw[1][g];
        const float4 va = __ldg(f4 + __float_as_int(ga.x) + tid);
        const float4 vb = __ldg(f4 + __float_as_int(gb.x) + tid);
        const float wa = ga.y, wb = gb.y;
        sa.x = fmaf(wa, va.x, sa.x); sa.y = fmaf(wa, va.y, sa.y);
        sa.z = fmaf(wa, va.z, sa.z); sa.w = fmaf(wa, va.w, sa.w);
        sb.x = fmaf(wb, vb.x, sb.x); sb.y = fmaf(wb, vb.y, sb.y);
        sb.z = fmaf(wb, vb.z, sb.z); sb.w = fmaf(wb, vb.w, sb.w);
    }
    const float4 xa = __ldg(f4 + xrowA + tid);
    const float4 xb = __ldg(f4 + xrowB + tid);

    // (sum w*row)/W - x   (weights normalized in reference)
    sa.x = sa.x * invwA - xa.x;  sa.y = sa.y * invwA - xa.y;
    sa.z = sa.z * invwA - xa.z;  sa.w = sa.w * invwA - xa.w;
    sb.x = sb.x * invwB - xb.x;  sb.y = sb.y * invwB - xb.y;
    sb.z = sb.z * invwB - xb.z;  sb.w = sb.w * invwB - xb.w;

    float lA = sa.x*sa.x + sa.y*sa.y + sa.z*sa.z + sa.w*sa.w;
    float lB = sb.x*sb.x + sb.y*sb.y + sb.z*sb.z + sb.w*sb.w;

#pragma unroll
    for (int off = 16; off > 0; off >>= 1) {
        lA += __shfl_down_sync(0xffffffffu, lA, off);
        lB += __shfl_down_sync(0xffffffffu, lB, off);
    }
    if (lane == 0) { red[0][w] = lA; red[1][w] = lB; }
    __syncthreads();
    const float rinvA = rsqrtf((red[0][0] + red[0][1] + red[0][2]) * (1.0f / CH) + RMSEPS);
    const float rinvB = rsqrtf((red[1][0] + red[1][1] + red[1][2]) * (1.0f / CH) + RMSEPS);

    const float4 kv  = __ldg((const float4*)knorm_w + tid);
    const float4 rvA = __ldg((const float4*)rf + (1 + n0) * CH4 + tid);
    const float4 rvB = __ldg((const float4*)rf + (1 + n1) * CH4 + tid);

    float4 oA, oB;
    oA.x = rvA.x + xa.x + sa.x * rinvA * kv.x;
    oA.y = rvA.y + xa.y + sa.y * rinvA * kv.y;
    oA.z = rvA.z + xa.z + sa.z * rinvA * kv.z;
    oA.w = rvA.w + xa.w + sa.w * rinvA * kv.w;
    oB.x = rvB.x + xb.x + sb.x * rinvB * kv.x;
    oB.y = rvB.y + xb.y + sb.y * rinvB * kv.y;
    oB.z = rvB.z + xb.z + sb.z * rinvB * kv.z;
    oB.w = rvB.w + xb.w + sb.w * rinvB * kv.w;
    ((float4*)out)[xrowA + tid] = oA;
    ((float4*)out)[xrowB + tid] = oB;
}

extern "C" void kernel_launch(void* const* d_in, const int* in_sizes, int n_in,
                              void* d_out, int out_size)
{
    const float* f        = (const float*)d_in[0];
    const float* distance = (const float*)d_in[1];
    const float* rf       = (const float*)d_in[2];
    const float* knorm_w  = (const float*)d_in[3];
    const int*   idx      = (const int*)d_in[4];
    float*       out      = (float*)d_out;

    K_Rectify_38216619000515_kernel<<<(BSZ * NPT) / 2, 96>>>(
        f, distance, rf, knorm_w, idx, out);
}

// round 15
// speedup vs baseline: 1.5016x; 1.0132x over previous
#include <cuda_runtime.h>

// Problem constants (static per reference)
#define BSZ   128
#define NTOT  129
#define NPT   128          // N
#define GS    16
#define CH    384          // channels
#define CH4   96           // CH / 4
#define EPSW  0.05f
#define RMSEPS 1e-6f

__global__ __launch_bounds__(96, 12)
void K_Rectify_38216619000515_kernel(
    const float* __restrict__ f,        // (B, NTOT, CH)
    const float* __restrict__ distance, // (B, N, GS)
    const float* __restrict__ rf,       // (NTOT, CH)
    const float* __restrict__ knorm_w,  // (CH,)
    const int*   __restrict__ idx,      // (B, N, GS), int32, values in [0, B*N)
    float*       __restrict__ out)      // (B, NTOT, CH)
{
    const int bid = blockIdx.x;          // 0..8191, two points per block
    const int bn0 = bid << 1;
    const int bn1 = bn0 | 1;
    const int tid = threadIdx.x;         // 0..95
    const int w   = tid >> 5;
    const int lane = tid & 31;

    __shared__ float2 sgw[2][GS];        // {row offset (int bits), weight}
    __shared__ float  red[2][3];

    if (tid < 2 * GS) {
        const int p  = tid >> 4;         // point 0/1
        const int g  = tid & 15;
        const int bn = bn0 + p;
        float d  = distance[bn * GS + g];
        float wt = 1.0f / (d + EPSW);
        int r    = idx[bn * GS + g] & (BSZ * NPT - 1);
        int off  = ((r >> 7) * NTOT + (r & 127) + 1) * CH4;   // float4 units
        sgw[p][g] = make_float2(__int_as_float(off), wt);
    }

    const int b0 = bn0 >> 7, n0 = bn0 & 127;
    const int b1 = bn1 >> 7, n1 = bn1 & 127;   // n1 is odd -> never 0

    // cls token passthrough (only point A can have n==0); 96 lanes == CH4
    if (n0 == 0) {
        ((float4*)out)[b0 * (NTOT * CH4) + tid] =
            __ldg((const float4*)f + b0 * (NTOT * CH4) + tid);
    }
    __syncthreads();

    float wsumA = 0.0f, wsumB = 0.0f;
#pragma unroll
    for (int g = 0; g < GS; ++g) { wsumA += sgw[0][g].y; wsumB += sgw[1][g].y; }
    const float invwA = 1.0f / wsumA;
    const float invwB = 1.0f / wsumB;

    const float4* f4 = (const float4*)f;
    const int xrowA = (b0 * NTOT + 1 + n0) * CH4;
    const int xrowB = (b1 * NTOT + 1 + n1) * CH4;

    float4 sa = make_float4(0.f,0.f,0.f,0.f);
    float4 sb = make_float4(0.f,0.f,0.f,0.f);
#pragma unroll
    for (int g = 0; g < GS; ++g) {
        const float2 ga = sgw[0][g];
        const float2 gb = sgw[1][g];
        // L1-bypass (cache-global): zero per-SM reuse stream, don't allocate L1
        const float4 va = __ldcg(f4 + __float_as_int(ga.x) + tid);
        const float4 vb = __ldcg(f4 + __float_as_int(gb.x) + tid);
        const float wa = ga.y, wb = gb.y;
        sa.x = fmaf(wa, va.x, sa.x); sa.y = fmaf(wa, va.y, sa.y);
        sa.z = fmaf(wa, va.z, sa.z); sa.w = fmaf(wa, va.w, sa.w);
        sb.x = fmaf(wb, vb.x, sb.x); sb.y = fmaf(wb, vb.y, sb.y);
        sb.z = fmaf(wb, vb.z, sb.z); sb.w = fmaf(wb, vb.w, sb.w);
    }
    const float4 xa = __ldcg(f4 + xrowA + tid);
    const float4 xb = __ldcg(f4 + xrowB + tid);

    // (sum w*row)/W - x   (weights normalized in reference)
    sa.x = sa.x * invwA - xa.x;  sa.y = sa.y * invwA - xa.y;
    sa.z = sa.z * invwA - xa.z;  sa.w = sa.w * invwA - xa.w;
    sb.x = sb.x * invwB - xb.x;  sb.y = sb.y * invwB - xb.y;
    sb.z = sb.z * invwB - xb.z;  sb.w = sb.w * invwB - xb.w;

    float lA = sa.x*sa.x + sa.y*sa.y + sa.z*sa.z + sa.w*sa.w;
    float lB = sb.x*sb.x + sb.y*sb.y + sb.z*sb.z + sb.w*sb.w;

#pragma unroll
    for (int off = 16; off > 0; off >>= 1) {
        lA += __shfl_down_sync(0xffffffffu, lA, off);
        lB += __shfl_down_sync(0xffffffffu, lB, off);
    }
    if (lane == 0) { red[0][w] = lA; red[1][w] = lB; }
    __syncthreads();
    const float rinvA = rsqrtf((red[0][0] + red[0][1] + red[0][2]) * (1.0f / CH) + RMSEPS);
    const float rinvB = rsqrtf((red[1][0] + red[1][1] + red[1][2]) * (1.0f / CH) + RMSEPS);

    const float4 kv  = __ldg((const float4*)knorm_w + tid);
    const float4 rvA = __ldg((const float4*)rf + (1 + n0) * CH4 + tid);
    const float4 rvB = __ldg((const float4*)rf + (1 + n1) * CH4 + tid);

    float4 oA, oB;
    oA.x = rvA.x + xa.x + sa.x * rinvA * kv.x;
    oA.y = rvA.y + xa.y + sa.y * rinvA * kv.y;
    oA.z = rvA.z + xa.z + sa.z * rinvA * kv.z;
    oA.w = rvA.w + xa.w + sa.w * rinvA * kv.w;
    oB.x = rvB.x + xb.x + sb.x * rinvB * kv.x;
    oB.y = rvB.y + xb.y + sb.y * rinvB * kv.y;
    oB.z = rvB.z + xb.z + sb.z * rinvB * kv.z;
    oB.w = rvB.w + xb.w + sb.w * rinvB * kv.w;
    ((float4*)out)[xrowA + tid] = oA;
    ((float4*)out)[xrowB + tid] = oB;
}

extern "C" void kernel_launch(void* const* d_in, const int* in_sizes, int n_in,
                              void* d_out, int out_size)
{
    const float* f        = (const float*)d_in[0];
    const float* distance = (const float*)d_in[1];
    const float* rf       = (const float*)d_in[2];
    const float* knorm_w  = (const float*)d_in[3];
    const int*   idx      = (const int*)d_in[4];
    float*       out      = (float*)d_out;

    K_Rectify_38216619000515_kernel<<<(BSZ * NPT) / 2, 96>>>(
        f, distance, rf, knorm_w, idx, out);
}

// round 16
// speedup vs baseline: 1.5033x; 1.0011x over previous
#include <cuda_runtime.h>

// Problem constants (static per reference)
#define BSZ   128
#define NTOT  129
#define NPT   128          // N
#define GS    16
#define CH    384          // channels
#define CH4   96           // CH / 4
#define EPSW  0.05f
#define RMSEPS 1e-6f

__global__ __launch_bounds__(96, 12)
void K_Rectify_38216619000515_kernel(
    const float* __restrict__ f,        // (B, NTOT, CH)
    const float* __restrict__ distance, // (B, N, GS)
    const float* __restrict__ rf,       // (NTOT, CH)
    const float* __restrict__ knorm_w,  // (CH,)
    const int*   __restrict__ idx,      // (B, N, GS), int32, values in [0, B*N)
    float*       __restrict__ out)      // (B, NTOT, CH)
{
    const int bid = blockIdx.x;          // 0..8191, two points per block
    const int bn0 = bid << 1;
    const int bn1 = bn0 | 1;
    const int tid = threadIdx.x;         // 0..95
    const int w   = tid >> 5;
    const int lane = tid & 31;

    __shared__ float2 sgw[2][GS];        // {row offset (int bits), weight}
    __shared__ float  red[2][3];

    if (tid < 2 * GS) {
        const int p  = tid >> 4;         // point 0/1
        const int g  = tid & 15;
        const int bn = bn0 + p;
        float d  = distance[bn * GS + g];
        float wt = 1.0f / (d + EPSW);
        int r    = idx[bn * GS + g] & (BSZ * NPT - 1);
        int off  = ((r >> 7) * NTOT + (r & 127) + 1) * CH4;   // float4 units
        sgw[p][g] = make_float2(__int_as_float(off), wt);
    }

    const int b0 = bn0 >> 7, n0 = bn0 & 127;
    const int b1 = bn1 >> 7, n1 = bn1 & 127;   // n1 is odd -> never 0

    // cls token passthrough (only point A can have n==0); 96 lanes == CH4
    if (n0 == 0) {
        ((float4*)out)[b0 * (NTOT * CH4) + tid] =
            __ldg((const float4*)f + b0 * (NTOT * CH4) + tid);
    }
    __syncthreads();

    float wsumA = 0.0f, wsumB = 0.0f;
#pragma unroll
    for (int g = 0; g < GS; ++g) { wsumA += sgw[0][g].y; wsumB += sgw[1][g].y; }
    const float invwA = 1.0f / wsumA;
    const float invwB = 1.0f / wsumB;

    const float4* f4 = (const float4*)f;
    const int xrowA = (b0 * NTOT + 1 + n0) * CH4;
    const int xrowB = (b1 * NTOT + 1 + n1) * CH4;

    float4 sa = make_float4(0.f,0.f,0.f,0.f);
    float4 sb = make_float4(0.f,0.f,0.f,0.f);
#pragma unroll
    for (int g = 0; g < GS; ++g) {
        const float2 ga = sgw[0][g];
        const float2 gb = sgw[1][g];
        const float4 va = __ldg(f4 + __float_as_int(ga.x) + tid);
        const float4 vb = __ldg(f4 + __float_as_int(gb.x) + tid);
        const float wa = ga.y, wb = gb.y;
        sa.x = fmaf(wa, va.x, sa.x); sa.y = fmaf(wa, va.y, sa.y);
        sa.z = fmaf(wa, va.z, sa.z); sa.w = fmaf(wa, va.w, sa.w);
        sb.x = fmaf(wb, vb.x, sb.x); sb.y = fmaf(wb, vb.y, sb.y);
        sb.z = fmaf(wb, vb.z, sb.z); sb.w = fmaf(wb, vb.w, sb.w);
    }
    const float4 xa = __ldg(f4 + xrowA + tid);
    const float4 xb = __ldg(f4 + xrowB + tid);

    // (sum w*row)/W - x   (valid because reference normalizes w, sum=1)
    sa.x = sa.x * invwA - xa.x;  sa.y = sa.y * invwA - xa.y;
    sa.z = sa.z * invwA - xa.z;  sa.w = sa.w * invwA - xa.w;
    sb.x = sb.x * invwB - xb.x;  sb.y = sb.y * invwB - xb.y;
    sb.z = sb.z * invwB - xb.z;  sb.w = sb.w * invwB - xb.w;

    float lA = sa.x*sa.x + sa.y*sa.y + sa.z*sa.z + sa.w*sa.w;
    float lB = sb.x*sb.x + sb.y*sb.y + sb.z*sb.z + sb.w*sb.w;

#pragma unroll
    for (int off = 16; off > 0; off >>= 1) {
        lA += __shfl_down_sync(0xffffffffu, lA, off);
        lB += __shfl_down_sync(0xffffffffu, lB, off);
    }
    if (lane == 0) { red[0][w] = lA; red[1][w] = lB; }
    __syncthreads();
    const float rinvA = rsqrtf((red[0][0] + red[0][1] + red[0][2]) * (1.0f / CH) + RMSEPS);
    const float rinvB = rsqrtf((red[1][0] + red[1][1] + red[1][2]) * (1.0f / CH) + RMSEPS);

    const float4 kv  = __ldg((const float4*)knorm_w + tid);
    const float4 rvA = __ldg((const float4*)rf + (1 + n0) * CH4 + tid);
    const float4 rvB = __ldg((const float4*)rf + (1 + n1) * CH4 + tid);

    float4 oA, oB;
    oA.x = rvA.x + xa.x + sa.x * rinvA * kv.x;
    oA.y = rvA.y + xa.y + sa.y * rinvA * kv.y;
    oA.z = rvA.z + xa.z + sa.z * rinvA * kv.z;
    oA.w = rvA.w + xa.w + sa.w * rinvA * kv.w;
    oB.x = rvB.x + xb.x + sb.x * rinvB * kv.x;
    oB.y = rvB.y + xb.y + sb.y * rinvB * kv.y;
    oB.z = rvB.z + xb.z + sb.z * rinvB * kv.z;
    oB.w = rvB.w + xb.w + sb.w * rinvB * kv.w;
    ((float4*)out)[xrowA + tid] = oA;
    ((float4*)out)[xrowB + tid] = oB;
}

extern "C" void kernel_launch(void* const* d_in, const int* in_sizes, int n_in,
                              void* d_out, int out_size)
{
    const float* f        = (const float*)d_in[0];
    const float* distance = (const float*)d_in[1];
    const float* rf       = (const float*)d_in[2];
    const float* knorm_w  = (const float*)d_in[3];
    const int*   idx      = (const int*)d_in[4];
    float*       out      = (float*)d_out;

    K_Rectify_38216619000515_kernel<<<(BSZ * NPT) / 2, 96>>>(
        f, distance, rf, knorm_w, idx, out);
}